// round 12
// baseline (speedup 1.0000x reference)
#include <cuda_runtime.h>
#include <math.h>
#include <stdint.h>

#define DMC 128
#define NLC 4
#define NSC 16
#define EDC 256
#define DTRC 8
#define EPSF 1e-5f
#define BSZ 16
#define NMC 80
#define LLC 500
#define NCC 35
#define MROWS (BSZ*LLC)       // 8000
#define PDIM (DTRC + 2*NSC)   // 40
#define CHUNKS 20
#define CLEN (LLC/CHUNKS)     // 25
#define EGRP (EDC/128)        // 2
#define STOT (BSZ*EGRP*CHUNKS) // 640
#define PGRP 10
#define PLEN (LLC/PGRP)       // 50

// ---------------- scratch (device globals) ----------------
__device__ float g_x[MROWS*DMC];
__device__ float g_xz[MROWS*2*EDC];
__device__ float g_xc[MROWS*EDC];
__device__ float g_dbc[MROWS*PDIM];
__device__ float g_y[MROWS*EDC];
__device__ float g_pooled_pp[BSZ*PGRP*DMC];
__device__ float g_cA[BSZ*CHUNKS*NSC*EDC];       // local aggregate P  [b][c][n][e]
__device__ float g_cB[BSZ*CHUNKS*NSC*EDC];       // local aggregate B  [b][c][n][e]
__device__ unsigned long long g_ticket;          // zero-init
__device__ unsigned int g_sflag[STOT];           // zero-init; monotone tags

__device__ __forceinline__ float siluf(float v){ return v / (1.f + __expf(-v)); }

__device__ __forceinline__ uint32_t f2tf(float x){
    uint32_t u; asm("cvt.rna.tf32.f32 %0, %1;" : "=r"(u) : "f"(x)); return u;
}
__device__ __forceinline__ void mma_tf32(float* c, const uint32_t* a, const uint32_t* b){
    asm volatile("mma.sync.aligned.m16n8k8.row.col.f32.tf32.tf32.f32 "
        "{%0,%1,%2,%3}, {%4,%5,%6,%7}, {%8,%9}, {%0,%1,%2,%3};"
        : "+f"(c[0]), "+f"(c[1]), "+f"(c[2]), "+f"(c[3])
        : "r"(a[0]), "r"(a[1]), "r"(a[2]), "r"(a[3]), "r"(b[0]), "r"(b[1]));
}

// =================================================================
// gemmtf: TF32 GEMM, TBK=16, warp tile 32x32. C[m][n]=sum_k A[m][k]B[n][k]
// AMODE: 1 rmsnorm-fused prologue, 3 stem gather
// EPI:   0 plain, 1 stem-bias+BN+silu
// =================================================================
template<int TBM, int TBN, int AMODE, int EPI>
__global__ void __launch_bounds__((TBM/32)*(TBN/32)*32) gemmtf(
    const float* __restrict__ A, const float* __restrict__ Bw, float* __restrict__ C,
    int M, int N, int Ktot, int lda, int ldb, int ldc,
    const float* __restrict__ p0, const float* __restrict__ p1,
    const float* __restrict__ p2, const float* __restrict__ p3,
    const float* __restrict__ p4, const float* __restrict__ p5,
    const float* __restrict__ p6)
{
    constexpr int TBK = 16;
    constexpr int KS = TBK + 4;
    constexpr int WN = TBN/32;
    constexpr int THREADS = (TBM/32)*(TBN/32)*32;
    constexpr int LA = TBM*TBK/(4*THREADS);
    constexpr int LB = TBN*TBK/(4*THREADS);
    __shared__ uint32_t As[2][TBM*KS];
    __shared__ uint32_t Bs[2][TBN*KS];
    __shared__ float rs_s[TBM];

    const int tid = threadIdx.x;
    const int warp = tid >> 5, lane = tid & 31;
    const int wr = warp / WN, wc = warp % WN;
    const int m0 = blockIdx.x*TBM, n0 = blockIdx.y*TBN;
    const int mw = wr*32, nw = wc*32;
    const int gr = lane >> 2, gc = lane & 3;

    if (AMODE==1) {
        int row = tid >> 1, half = tid & 1;
        if (row < TBM) {
            const float4* rp = (const float4*)&A[(m0+row)*lda + half*(DMC/2)];
            float s = 0.f;
            #pragma unroll
            for (int i=0;i<DMC/8;i++){ float4 v=rp[i]; s += v.x*v.x+v.y*v.y+v.z*v.z+v.w*v.w; }
            s += __shfl_xor_sync(0xffffffffu, s, 1);
            if (!half) rs_s[row] = rsqrtf(s*(1.f/DMC)+EPSF);
        }
        __syncthreads();
    }

    float acc[2][4][4];
    #pragma unroll
    for (int i=0;i<2;i++)
        #pragma unroll
        for (int j=0;j<4;j++)
            #pragma unroll
            for (int q=0;q<4;q++) acc[i][j][q]=0.f;

    uint32_t ra[LA][4], rb[LB][4];

    auto ldg = [&](int k0){
        #pragma unroll
        for (int i=0;i<LA;i++){
            int s = i*THREADS + tid;
            int mo = s>>2, kq = s&3;
            int m = m0+mo, k = k0 + kq*4;
            float4 v = make_float4(0.f,0.f,0.f,0.f);
            if (m < M && k < Ktot) {
                if (AMODE==3) {
                    int b = m / LLC, l = m - b*LLC;
                    float t[4];
                    #pragma unroll
                    for (int j=0;j<4;j++){
                        int kk = k+j; int c = kk/5, kt = kk - c*5;
                        int pos = l - 2 + kt;
                        t[j] = (pos>=0 && pos<LLC) ? p0[(b*NMC+c)*LLC+pos] : 0.f;
                    }
                    v = make_float4(t[0],t[1],t[2],t[3]);
                } else {
                    v = *(const float4*)&A[m*lda + k];
                    if (AMODE==1) {
                        float sc = rs_s[mo];
                        float4 w = *(const float4*)&p1[k];
                        v.x *= sc*w.x; v.y *= sc*w.y; v.z *= sc*w.z; v.w *= sc*w.w;
                    }
                }
            }
            ra[i][0]=f2tf(v.x); ra[i][1]=f2tf(v.y); ra[i][2]=f2tf(v.z); ra[i][3]=f2tf(v.w);
        }
        #pragma unroll
        for (int i=0;i<LB;i++){
            int s = i*THREADS + tid;
            int no = s>>2, kq = s&3;
            int n = n0+no, k = k0+kq*4;
            float4 v = make_float4(0.f,0.f,0.f,0.f);
            if (n < N && k < Ktot) v = *(const float4*)&Bw[n*ldb + k];
            rb[i][0]=f2tf(v.x); rb[i][1]=f2tf(v.y); rb[i][2]=f2tf(v.z); rb[i][3]=f2tf(v.w);
        }
    };
    auto sts = [&](int st){
        #pragma unroll
        for (int i=0;i<LA;i++){
            int s=i*THREADS+tid; int mo=s>>2, kq=s&3;
            uint32_t* dst = &As[st][mo*KS + kq*4];
            dst[0]=ra[i][0]; dst[1]=ra[i][1]; dst[2]=ra[i][2]; dst[3]=ra[i][3];
        }
        #pragma unroll
        for (int i=0;i<LB;i++){
            int s=i*THREADS+tid; int no=s>>2, kq=s&3;
            uint32_t* dst = &Bs[st][no*KS + kq*4];
            dst[0]=rb[i][0]; dst[1]=rb[i][1]; dst[2]=rb[i][2]; dst[3]=rb[i][3];
        }
    };

    const int nk = (Ktot + TBK - 1)/TBK;
    ldg(0); sts(0); __syncthreads();
    for (int kt=0; kt<nk; kt++){
        int st = kt&1;
        if (kt+1<nk) ldg((kt+1)*TBK);
        #pragma unroll
        for (int k8=0;k8<2;k8++){
            uint32_t af[2][4], bf[4][2];
            #pragma unroll
            for (int mi=0;mi<2;mi++){
                const uint32_t* base = &As[st][(mw + mi*16 + gr)*KS + k8*8 + gc];
                af[mi][0]=base[0]; af[mi][1]=base[8*KS];
                af[mi][2]=base[4]; af[mi][3]=base[8*KS+4];
            }
            #pragma unroll
            for (int ni=0;ni<4;ni++){
                const uint32_t* base = &Bs[st][(nw + ni*8 + gr)*KS + k8*8 + gc];
                bf[ni][0]=base[0]; bf[ni][1]=base[4];
            }
            #pragma unroll
            for (int mi=0;mi<2;mi++)
                #pragma unroll
                for (int ni=0;ni<4;ni++)
                    mma_tf32(acc[mi][ni], af[mi], bf[ni]);
        }
        if (kt+1<nk){ sts(st^1); __syncthreads(); }
    }

    #pragma unroll
    for (int mi=0;mi<2;mi++){
        #pragma unroll
        for (int ni=0;ni<4;ni++){
            int n = n0 + nw + ni*8 + gc*2;
            if (n >= N) continue;
            #pragma unroll
            for (int half=0; half<2; half++){
                int m = m0 + mw + mi*16 + gr + half*8;
                if (m >= M) continue;
                float v0 = acc[mi][ni][half*2+0];
                float v1 = acc[mi][ni][half*2+1];
                if (EPI==1){
                    float t0 = v0 + p2[n];
                    t0 = (t0 - p3[n]) * rsqrtf(p4[n]+EPSF) * p5[n] + p6[n];
                    v0 = siluf(t0);
                    float t1 = v1 + p2[n+1];
                    t1 = (t1 - p3[n+1]) * rsqrtf(p4[n+1]+EPSF) * p5[n+1] + p6[n+1];
                    v1 = siluf(t1);
                }
                *(float2*)&C[m*ldc+n] = make_float2(v0, v1);
            }
        }
    }
}

// =================================================================
// gemmks: TF32 GEMM with warp-split-K (KSPLIT=2), TBK=32
// AMODE: 0 plain, 4 fused depthwise conv+silu over g_xz (side-writes g_xc)
// EPI:   0 plain, 2 residual add into C
// =================================================================
template<int TBM, int TBN, int AMODE, int EPI>
__global__ void __launch_bounds__((TBM/32)*(TBN/32)*64) gemmks(
    const float* __restrict__ A, const float* __restrict__ Bw, float* __restrict__ C,
    int M, int N, int Ktot, int lda, int ldb, int ldc,
    const float* __restrict__ p1, const float* __restrict__ p2)
{
    constexpr int TBK = 32;
    constexpr int KS = TBK + 4;
    constexpr int WN = TBN/32;
    constexpr int NOUT = (TBM/32)*(TBN/32);
    constexpr int THREADS = NOUT*64;
    constexpr int LA = TBM*TBK/(4*THREADS);
    constexpr int LB = TBN*TBK/(4*THREADS);
    constexpr int GEMM_BYTES = 2*(TBM+TBN)*KS*4;
    constexpr int RED_BYTES  = NOUT*32*33*4;
    constexpr int SMB = GEMM_BYTES > RED_BYTES ? GEMM_BYTES : RED_BYTES;
    __shared__ __align__(16) char smbuf[SMB];
    uint32_t* Asp = (uint32_t*)smbuf;
    uint32_t* Bsp = Asp + 2*TBM*KS;

    const int tid = threadIdx.x;
    const int warp = tid >> 5, lane = tid & 31;
    const int kg = warp / NOUT;
    const int wo = warp % NOUT;
    const int wr = wo / WN, wc = wo % WN;
    const int m0 = blockIdx.x*TBM, n0 = blockIdx.y*TBN;
    const int mw = wr*32, nw = wc*32;
    const int gr = lane >> 2, gc = lane & 3;

    float acc[2][4][4];
    #pragma unroll
    for (int i=0;i<2;i++)
        #pragma unroll
        for (int j=0;j<4;j++)
            #pragma unroll
            for (int q=0;q<4;q++) acc[i][j][q]=0.f;

    uint32_t ra[LA][4], rb[LB][4];

    auto ldg = [&](int k0){
        #pragma unroll
        for (int i=0;i<LA;i++){
            int s = i*THREADS + tid;
            int mo = s>>3, kq = s&7;
            int m = m0+mo, k = k0 + kq*4;
            float4 v = make_float4(0.f,0.f,0.f,0.f);
            if (m < M && k < Ktot) {
                if (AMODE==4) {
                    int l = m % LLC;
                    v = *(const float4*)&p2[k];
                    float4 w0 = *(const float4*)&p1[(k+0)*4];
                    float4 w1 = *(const float4*)&p1[(k+1)*4];
                    float4 w2 = *(const float4*)&p1[(k+2)*4];
                    float4 w3 = *(const float4*)&p1[(k+3)*4];
                    const float* wj[4] = {&w0.x, &w1.x, &w2.x, &w3.x};
                    #pragma unroll
                    for (int t=0;t<4;t++){
                        if (l - 3 + t >= 0) {
                            float4 xv = *(const float4*)&A[(m-3+t)*(2*EDC) + k];
                            v.x += xv.x * wj[0][t];
                            v.y += xv.y * wj[1][t];
                            v.z += xv.z * wj[2][t];
                            v.w += xv.w * wj[3][t];
                        }
                    }
                    v.x = siluf(v.x); v.y = siluf(v.y);
                    v.z = siluf(v.z); v.w = siluf(v.w);
                    *(float4*)&g_xc[m*EDC + k] = v;
                } else {
                    v = *(const float4*)&A[m*lda + k];
                }
            }
            ra[i][0]=f2tf(v.x); ra[i][1]=f2tf(v.y); ra[i][2]=f2tf(v.z); ra[i][3]=f2tf(v.w);
        }
        #pragma unroll
        for (int i=0;i<LB;i++){
            int s = i*THREADS + tid;
            int no = s>>3, kq = s&7;
            int n = n0+no, k = k0+kq*4;
            float4 v = make_float4(0.f,0.f,0.f,0.f);
            if (n < N && k < Ktot) v = *(const float4*)&Bw[n*ldb + k];
            rb[i][0]=f2tf(v.x); rb[i][1]=f2tf(v.y); rb[i][2]=f2tf(v.z); rb[i][3]=f2tf(v.w);
        }
    };
    auto sts = [&](int st){
        #pragma unroll
        for (int i=0;i<LA;i++){
            int s=i*THREADS+tid; int mo=s>>3, kq=s&7;
            uint32_t* dst = &Asp[st*TBM*KS + mo*KS + kq*4];
            dst[0]=ra[i][0]; dst[1]=ra[i][1]; dst[2]=ra[i][2]; dst[3]=ra[i][3];
        }
        #pragma unroll
        for (int i=0;i<LB;i++){
            int s=i*THREADS+tid; int no=s>>3, kq=s&7;
            uint32_t* dst = &Bsp[st*TBN*KS + no*KS + kq*4];
            dst[0]=rb[i][0]; dst[1]=rb[i][1]; dst[2]=rb[i][2]; dst[3]=rb[i][3];
        }
    };

    const int nkt = Ktot/TBK;
    ldg(0); sts(0); __syncthreads();
    for (int kt=0; kt<nkt; kt++){
        int st = kt&1;
        if (kt+1<nkt) ldg((kt+1)*TBK);
        #pragma unroll
        for (int k8=0;k8<2;k8++){
            int col = kg*16 + k8*8;
            uint32_t af[2][4], bf[4][2];
            #pragma unroll
            for (int mi=0;mi<2;mi++){
                const uint32_t* base = &Asp[st*TBM*KS + (mw + mi*16 + gr)*KS + col + gc];
                af[mi][0]=base[0]; af[mi][1]=base[8*KS];
                af[mi][2]=base[4]; af[mi][3]=base[8*KS+4];
            }
            #pragma unroll
            for (int ni=0;ni<4;ni++){
                const uint32_t* base = &Bsp[st*TBN*KS + (nw + ni*8 + gr)*KS + col + gc];
                bf[ni][0]=base[0]; bf[ni][1]=base[4];
            }
            #pragma unroll
            for (int mi=0;mi<2;mi++)
                #pragma unroll
                for (int ni=0;ni<4;ni++)
                    mma_tf32(acc[mi][ni], af[mi], bf[ni]);
        }
        if (kt+1<nkt){ sts(st^1); __syncthreads(); }
    }

    __syncthreads();
    float* red = (float*)smbuf;
    if (kg==1){
        #pragma unroll
        for (int mi=0;mi<2;mi++)
            #pragma unroll
            for (int ni=0;ni<4;ni++)
                #pragma unroll
                for (int q=0;q<4;q++)
                    red[(wo*32+lane)*33 + mi*16+ni*4+q] = acc[mi][ni][q];
    }
    __syncthreads();
    if (kg==0){
        #pragma unroll
        for (int mi=0;mi<2;mi++)
            #pragma unroll
            for (int ni=0;ni<4;ni++)
                #pragma unroll
                for (int q=0;q<4;q++)
                    acc[mi][ni][q] += red[(wo*32+lane)*33 + mi*16+ni*4+q];

        #pragma unroll
        for (int mi=0;mi<2;mi++){
            #pragma unroll
            for (int ni=0;ni<4;ni++){
                int n = n0 + nw + ni*8 + gc*2;
                if (n >= N) continue;
                #pragma unroll
                for (int half=0; half<2; half++){
                    int m = m0 + mw + mi*16 + gr + half*8;
                    if (m >= M) continue;
                    float v0 = acc[mi][ni][half*2+0];
                    float v1 = acc[mi][ni][half*2+1];
                    if (EPI==2){
                        float2 c = *(const float2*)&C[m*ldc+n];
                        v0 += c.x; v1 += c.y;
                    }
                    *(float2*)&C[m*ldc+n] = make_float2(v0, v1);
                }
            }
        }
    }
}

// ---------------- single-pass scan, aggregate lookback, vectorized loads ------
__device__ __forceinline__ float softplusf(float a){
    return (a > 20.f) ? a : __logf(1.f + __expf(a));
}

// log-depth powers: w[k] = t1^(k+1), k = 0..15
__device__ __forceinline__ void pow16(float t1, float* w){
    float t2 = t1*t1, t4 = t2*t2, t8 = t4*t4;
    w[0]=t1; w[1]=t2; w[2]=t2*t1; w[3]=t4;
    w[4]=t4*w[0]; w[5]=t4*w[1]; w[6]=t4*w[2]; w[7]=t8;
    #pragma unroll
    for (int k=0;k<8;k++) w[8+k] = t8*w[k];
}

__global__ void __launch_bounds__(128) scan_sp(
    const float* __restrict__ Alog, const float* __restrict__ Dp,
    const float* __restrict__ dtW, const float* __restrict__ dtb)
{
    __shared__ float s_sz[CLEN][128];     // silu(z), 12.8 KB
    __shared__ unsigned long long s_t;
    if (threadIdx.x==0) s_t = atomicAdd(&g_ticket, 1ULL);
    __syncthreads();
    const unsigned long long tk = s_t;
    const int pos = (int)(tk % STOT);
    const unsigned tag = (unsigned)(tk / STOT) + 1u;
    const int c   = pos / (BSZ*EGRP);
    const int rem = pos % (BSZ*EGRP);
    const int b   = rem / EGRP, eg = rem % EGRP;
    const int e   = eg*128 + threadIdx.x;
    const int fibase = (b*EGRP + eg)*CHUNKS;

    float a0 = -__expf(Alog[e*NSC]);
    bool ok = true;
    #pragma unroll
    for (int n = 0; n < NSC; n++) {
        float an = -__expf(Alog[e*NSC + n]);
        if (fabsf(an - a0*(float)(n+1)) > 1e-4f*fmaxf(1.f, fabsf(an))) ok = false;
    }
    float dw[DTRC];
    *(float4*)&dw[0] = *(const float4*)&dtW[e*DTRC];
    *(float4*)&dw[4] = *(const float4*)&dtW[e*DTRC+4];
    const float dbias = dtb[e];
    const float Dv = Dp[e];

    float h[NSC];
    #pragma unroll
    for (int n = 0; n < NSC; n++) h[n] = 0.f;
    float S[CLEN];
    float Sc = 0.f;

    const int l0 = c*CLEN;
    const float* xcp = g_xc  + (b*LLC+l0)*EDC + e;
    const float* dbc = g_dbc + (b*LLC+l0)*PDIM;
    const float* zp  = g_xz  + (b*LLC+l0)*(2*EDC) + EDC + e;
    float* yo = g_y + (b*LLC+l0)*EDC + e;

    // preload silu(z)
    #pragma unroll 5
    for (int l = 0; l < CLEN; l++)
        s_sz[l][threadIdx.x] = siluf(zp[l*(2*EDC)]);

    // local scan sweep (h_init = 0), emit gated local y, record cumulative d
    #pragma unroll 5
    for (int l = 0; l < CLEN; l++) {
        const float4* rv = (const float4*)(dbc + l*PDIM);
        float4 q0 = rv[0], q1 = rv[1];
        float Bv[NSC], Cv[NSC];
        *(float4*)&Bv[0]  = rv[2]; *(float4*)&Bv[4]  = rv[3];
        *(float4*)&Bv[8]  = rv[4]; *(float4*)&Bv[12] = rv[5];
        *(float4*)&Cv[0]  = rv[6]; *(float4*)&Cv[4]  = rv[7];
        *(float4*)&Cv[8]  = rv[8]; *(float4*)&Cv[12] = rv[9];
        float dacc = dbias
            + q0.x*dw[0] + q0.y*dw[1] + q0.z*dw[2] + q0.w*dw[3]
            + q1.x*dw[4] + q1.y*dw[5] + q1.z*dw[6] + q1.w*dw[7];
        float d = softplusf(dacc);
        Sc += d;
        S[l] = Sc;
        float xv = xcp[l*EDC];
        float dx = d*xv;
        float ys0 = 0.f, ys1 = 0.f, ys2 = 0.f, ys3 = 0.f;
        if (ok) {
            float w[NSC];
            pow16(__expf(d * a0), w);
            #pragma unroll
            for (int n = 0; n < NSC; n++) {
                h[n] = w[n]*h[n] + dx*Bv[n];
                float t = h[n]*Cv[n];
                if ((n&3)==0) ys0 += t; else if ((n&3)==1) ys1 += t;
                else if ((n&3)==2) ys2 += t; else ys3 += t;
            }
        } else {
            #pragma unroll
            for (int n = 0; n < NSC; n++) {
                float dA = __expf(d * (-__expf(Alog[e*NSC + n])));
                h[n] = dA*h[n] + dx*Bv[n];
                ys0 += h[n]*Cv[n];
            }
        }
        yo[l*EDC] = ((ys0+ys1)+(ys2+ys3) + Dv*xv) * s_sz[l][threadIdx.x];
    }

    // publish LOCAL aggregates immediately
    if (c < CHUNKS-1) {
        const int base = ((b*CHUNKS + c)*NSC)*EDC + e;
        if (ok) {
            float w[NSC];
            pow16(__expf(a0*Sc), w);
            #pragma unroll
            for (int n = 0; n < NSC; n++) {
                g_cA[base + n*EDC] = w[n];
                g_cB[base + n*EDC] = h[n];
            }
        } else {
            #pragma unroll
            for (int n = 0; n < NSC; n++) {
                float an = -__expf(Alog[e*NSC + n]);
                g_cA[base + n*EDC] = __expf(an*Sc);
                g_cB[base + n*EDC] = h[n];
            }
        }
        __threadfence();
        __syncthreads();
        if (threadIdx.x == 0) ((volatile unsigned*)g_sflag)[fibase + c] = tag;
    }

    if (c == 0) return;

    // parallel wait: thread j polls predecessor j's flag
    if (threadIdx.x < c) {
        volatile unsigned* fl = (volatile unsigned*)g_sflag;
        while (fl[fibase + threadIdx.x] != tag) { __nanosleep(40); }
    }
    __syncthreads();
    __threadfence();

    // fold predecessors' aggregates: h_init = fold_{j=0..c-1} (P_j*h + B_j)
    float hi[NSC];
    #pragma unroll
    for (int n = 0; n < NSC; n++) hi[n] = 0.f;
    for (int j = 0; j < c; j++) {
        const int base = ((b*CHUNKS + j)*NSC)*EDC + e;
        #pragma unroll
        for (int n = 0; n < NSC; n++)
            hi[n] = g_cA[base + n*EDC]*hi[n] + g_cB[base + n*EDC];
    }

    // correction sweep: y_l += gate * sum_n w^n * hi[n] * C_l[n]
    if (ok) {
        #pragma unroll 5
        for (int l = 0; l < CLEN; l++) {
            const float4* rv = (const float4*)(dbc + l*PDIM);
            float Cv[NSC];
            *(float4*)&Cv[0]  = rv[6]; *(float4*)&Cv[4]  = rv[7];
            *(float4*)&Cv[8]  = rv[8]; *(float4*)&Cv[12] = rv[9];
            float w[NSC];
            pow16(__expf(a0*S[l]), w);
            float c0 = 0.f, c1 = 0.f, c2 = 0.f, c3 = 0.f;
            #pragma unroll
            for (int n = 0; n < NSC; n++) {
                float t = w[n]*hi[n]*Cv[n];
                if ((n&3)==0) c0 += t; else if ((n&3)==1) c1 += t;
                else if ((n&3)==2) c2 += t; else c3 += t;
            }
            yo[l*EDC] += ((c0+c1)+(c2+c3)) * s_sz[l][threadIdx.x];
        }
    } else {
        float an[NSC];
        #pragma unroll
        for (int n = 0; n < NSC; n++) an[n] = -__expf(Alog[e*NSC + n]);
        for (int l = 0; l < CLEN; l++) {
            const float* row = dbc + l*PDIM;
            float corr = 0.f;
            #pragma unroll
            for (int n = 0; n < NSC; n++)
                corr += __expf(an[n]*S[l])*hi[n]*row[DTRC + NSC + n];
            yo[l*EDC] += corr * s_sz[l][threadIdx.x];
        }
    }
}

// ---------------- tail kernels ----------------
__global__ void __launch_bounds__(128) pool2_k() {
    __shared__ float s_mu[PLEN], s_rs[PLEN];
    const int b = blockIdx.x, g = blockIdx.y;
    const int tid = threadIdx.x;
    const int warp = tid >> 5, lane = tid & 31;
    const int mbase = b*LLC + g*PLEN;

    for (int l = warp; l < PLEN; l += 4) {
        float4 v = ((const float4*)(g_x + (mbase+l)*DMC))[lane];
        float s  = v.x + v.y + v.z + v.w;
        float s2 = v.x*v.x + v.y*v.y + v.z*v.z + v.w*v.w;
        #pragma unroll
        for (int off = 16; off > 0; off >>= 1) {
            s  += __shfl_xor_sync(0xffffffffu, s,  off);
            s2 += __shfl_xor_sync(0xffffffffu, s2, off);
        }
        if (lane == 0) {
            float mu = s * (1.f/DMC);
            float var = s2 * (1.f/DMC) - mu*mu;
            s_mu[l] = mu;
            s_rs[l] = rsqrtf(var + EPSF);
        }
    }
    __syncthreads();

    const int d = tid;
    float s = 0.f;
    #pragma unroll 5
    for (int l = 0; l < PLEN; l++)
        s += (g_x[(mbase+l)*DMC + d] - s_mu[l]) * s_rs[l];
    g_pooled_pp[(b*PGRP + g)*DMC + d] = s;
}

__global__ void head_k(const float* __restrict__ lw, const float* __restrict__ lb,
                       const float* __restrict__ eW, const float* __restrict__ eb,
                       const float* __restrict__ cW, const float* __restrict__ cb,
                       const float* __restrict__ wW, const float* __restrict__ wb,
                       float* __restrict__ out) {
    __shared__ float ps[DMC], es[DMC];
    int b = blockIdx.x, t = threadIdx.x;
    float s = 0.f;
    #pragma unroll
    for (int g = 0; g < PGRP; g++) s += g_pooled_pp[(b*PGRP + g)*DMC + t];
    ps[t] = s * (1.f/LLC) * lw[t] + lb[t];
    __syncthreads();
    float acc = eb[t];
    #pragma unroll 4
    for (int k = 0; k < DMC; k++) acc += ps[k]*eW[t*DMC + k];
    float em = acc / (1.f + expf(-acc));
    es[t] = em;
    out[BSZ*NCC + BSZ + b*DMC + t] = em;
    __syncthreads();
    if (t < NCC) {
        float a = cb[t];
        #pragma unroll 4
        for (int k = 0; k < DMC; k++) a += es[k]*cW[t*DMC + k];
        out[b*NCC + t] = a;
    }
    if (t == NCC) {
        float a = wb[0];
        #pragma unroll 4
        for (int k = 0; k < DMC; k++) a += es[k]*wW[k];
        out[BSZ*NCC + b] = a;
    }
}

// ---------------- launch ----------------
extern "C" void kernel_launch(void* const* d_in, const int* in_sizes, int n_in,
                              void* d_out, int out_size) {
    const float* feat    = (const float*)d_in[0];
    const float* stem_w  = (const float*)d_in[1];
    const float* stem_b  = (const float*)d_in[2];
    const float* bn_g    = (const float*)d_in[3];
    const float* bn_b    = (const float*)d_in[4];
    const float* bn_m    = (const float*)d_in[5];
    const float* bn_v    = (const float*)d_in[6];
    const float* norm_w  = (const float*)d_in[7];
    const float* inW     = (const float*)d_in[8];
    const float* convw   = (const float*)d_in[9];
    const float* convb   = (const float*)d_in[10];
    const float* xW      = (const float*)d_in[11];
    const float* dtW     = (const float*)d_in[12];
    const float* dtb     = (const float*)d_in[13];
    const float* Alog    = (const float*)d_in[14];
    const float* Dp      = (const float*)d_in[15];
    const float* oW      = (const float*)d_in[16];
    const float* ln_w    = (const float*)d_in[17];
    const float* ln_b    = (const float*)d_in[18];
    const float* eW      = (const float*)d_in[19];
    const float* eb      = (const float*)d_in[20];
    const float* cW      = (const float*)d_in[21];
    const float* cb      = (const float*)d_in[22];
    const float* wW      = (const float*)d_in[23];
    const float* wb      = (const float*)d_in[24];
    float* out = (float*)d_out;

    static float *px=nullptr, *pxz=nullptr, *pdbc=nullptr, *py=nullptr;
    if (!px) {
        cudaGetSymbolAddress((void**)&px,   g_x);
        cudaGetSymbolAddress((void**)&pxz,  g_xz);
        cudaGetSymbolAddress((void**)&pdbc, g_dbc);
        cudaGetSymbolAddress((void**)&py,   g_y);
    }

    const int MT64 = MROWS/64;   // 125
    const int MT32 = MROWS/32;   // 250

    // stem: M=8000, N=128, K=400 (gathered A) + BN + silu -> g_x
    gemmtf<64,64,3,1><<<dim3(MT64, DMC/64), 128>>>(
        nullptr, stem_w, px, MROWS, DMC, NMC*5, 0, NMC*5, DMC,
        feat, nullptr, stem_b, bn_m, bn_v, bn_g, bn_b);

    for (int i = 0; i < NLC; i++) {
        const float* nw_i  = norm_w + i*DMC;
        const float* inW_i = inW    + i*(2*EDC)*DMC;
        const float* cw_i  = convw  + i*EDC*4;
        const float* cb_i  = convb  + i*EDC;
        const float* xW_i  = xW     + i*PDIM*EDC;
        const float* dtW_i = dtW    + i*EDC*DTRC;
        const float* dtb_i = dtb    + i*EDC;
        const float* Al_i  = Alog   + i*EDC*NSC;
        const float* D_i   = Dp     + i*EDC;
        const float* oW_i  = oW     + i*DMC*EDC;

        // rmsnorm(prologue) + in_proj: M=8000, N=512, K=128 -> g_xz
        gemmtf<64,64,1,0><<<dim3(MT64, (2*EDC)/64), 128>>>(
            px, inW_i, pxz, MROWS, 2*EDC, DMC, DMC, DMC, 2*EDC,
            nullptr, nw_i, nullptr, nullptr, nullptr, nullptr, nullptr);
        // fused conv+silu (side-writes g_xc) + x_proj -> g_dbc
        gemmks<32,64,4,0><<<dim3(MT32, 1), 128>>>(
            pxz, xW_i, pdbc, MROWS, PDIM, EDC, 2*EDC, EDC, PDIM, cw_i, cb_i);
        // single-pass scan, aggregate lookback, gated y -> g_y
        scan_sp<<<STOT, 128>>>(Al_i, D_i, dtW_i, dtb_i);
        // out_proj + residual -> g_x
        gemmks<32,128,0,2><<<dim3(MT32, 1), 256>>>(
            py, oW_i, px, MROWS, DMC, EDC, EDC, EDC, DMC, nullptr, nullptr);
    }

    pool2_k<<<dim3(BSZ, PGRP), 128>>>();
    head_k<<<BSZ, DMC>>>(ln_w, ln_b, eW, eb, cW, cb, wW, wb, out);
    (void)in_sizes; (void)n_in; (void)out_size;
}

// round 13
// speedup vs baseline: 1.1594x; 1.1594x over previous
#include <cuda_runtime.h>
#include <math.h>
#include <stdint.h>

#define DMC 128
#define NLC 4
#define NSC 16
#define EDC 256
#define DTRC 8
#define EPSF 1e-5f
#define BSZ 16
#define NMC 80
#define LLC 500
#define NCC 35
#define MROWS (BSZ*LLC)       // 8000
#define PDIM (DTRC + 2*NSC)   // 40
#define CHUNKS 20
#define CLEN (LLC/CHUNKS)     // 25
#define EGRP (EDC/128)        // 2
#define STOT (BSZ*EGRP*CHUNKS) // 640
#define PGRP 10
#define PLEN (LLC/PGRP)       // 50

// ---------------- scratch (device globals) ----------------
__device__ float g_x[MROWS*DMC];
__device__ float g_xz[MROWS*2*EDC];
__device__ float g_xc[MROWS*EDC];
__device__ float g_dbc[MROWS*PDIM];
__device__ float g_y[MROWS*EDC];
__device__ float g_pooled_pp[BSZ*PGRP*DMC];
__device__ float g_cA[BSZ*CHUNKS*NSC*EDC];       // local aggregate P  [b][c][n][e]
__device__ float g_cB[BSZ*CHUNKS*NSC*EDC];       // local aggregate B  [b][c][n][e]
__device__ unsigned long long g_ticket;          // zero-init
__device__ unsigned int g_sflag[STOT];           // zero-init; monotone tags

__device__ __forceinline__ float siluf(float v){ return v / (1.f + __expf(-v)); }

__device__ __forceinline__ uint32_t f2tf(float x){
    uint32_t u; asm("cvt.rna.tf32.f32 %0, %1;" : "=r"(u) : "f"(x)); return u;
}
__device__ __forceinline__ void mma_tf32(float* c, const uint32_t* a, const uint32_t* b){
    asm volatile("mma.sync.aligned.m16n8k8.row.col.f32.tf32.tf32.f32 "
        "{%0,%1,%2,%3}, {%4,%5,%6,%7}, {%8,%9}, {%0,%1,%2,%3};"
        : "+f"(c[0]), "+f"(c[1]), "+f"(c[2]), "+f"(c[3])
        : "r"(a[0]), "r"(a[1]), "r"(a[2]), "r"(a[3]), "r"(b[0]), "r"(b[1]));
}

// =================================================================
// gemmtf: TF32 GEMM, TBK=16, warp tile 32x32. C[m][n]=sum_k A[m][k]B[n][k]
// AMODE: 1 rmsnorm-fused prologue, 3 stem gather
// EPI:   0 plain, 1 stem-bias+BN+silu
// =================================================================
template<int TBM, int TBN, int AMODE, int EPI>
__global__ void __launch_bounds__((TBM/32)*(TBN/32)*32) gemmtf(
    const float* __restrict__ A, const float* __restrict__ Bw, float* __restrict__ C,
    int M, int N, int Ktot, int lda, int ldb, int ldc,
    const float* __restrict__ p0, const float* __restrict__ p1,
    const float* __restrict__ p2, const float* __restrict__ p3,
    const float* __restrict__ p4, const float* __restrict__ p5,
    const float* __restrict__ p6)
{
    constexpr int TBK = 16;
    constexpr int KS = TBK + 4;
    constexpr int WN = TBN/32;
    constexpr int THREADS = (TBM/32)*(TBN/32)*32;
    constexpr int LA = TBM*TBK/(4*THREADS);
    constexpr int LB = TBN*TBK/(4*THREADS);
    __shared__ uint32_t As[2][TBM*KS];
    __shared__ uint32_t Bs[2][TBN*KS];
    __shared__ float rs_s[TBM];

    const int tid = threadIdx.x;
    const int warp = tid >> 5, lane = tid & 31;
    const int wr = warp / WN, wc = warp % WN;
    const int m0 = blockIdx.x*TBM, n0 = blockIdx.y*TBN;
    const int mw = wr*32, nw = wc*32;
    const int gr = lane >> 2, gc = lane & 3;

    if (AMODE==1) {
        int row = tid >> 1, half = tid & 1;
        if (row < TBM) {
            const float4* rp = (const float4*)&A[(m0+row)*lda + half*(DMC/2)];
            float s = 0.f;
            #pragma unroll
            for (int i=0;i<DMC/8;i++){ float4 v=rp[i]; s += v.x*v.x+v.y*v.y+v.z*v.z+v.w*v.w; }
            s += __shfl_xor_sync(0xffffffffu, s, 1);
            if (!half) rs_s[row] = rsqrtf(s*(1.f/DMC)+EPSF);
        }
        __syncthreads();
    }

    float acc[2][4][4];
    #pragma unroll
    for (int i=0;i<2;i++)
        #pragma unroll
        for (int j=0;j<4;j++)
            #pragma unroll
            for (int q=0;q<4;q++) acc[i][j][q]=0.f;

    uint32_t ra[LA][4], rb[LB][4];

    auto ldg = [&](int k0){
        #pragma unroll
        for (int i=0;i<LA;i++){
            int s = i*THREADS + tid;
            int mo = s>>2, kq = s&3;
            int m = m0+mo, k = k0 + kq*4;
            float4 v = make_float4(0.f,0.f,0.f,0.f);
            if (m < M && k < Ktot) {
                if (AMODE==3) {
                    int b = m / LLC, l = m - b*LLC;
                    float t[4];
                    #pragma unroll
                    for (int j=0;j<4;j++){
                        int kk = k+j; int c = kk/5, kt = kk - c*5;
                        int pos = l - 2 + kt;
                        t[j] = (pos>=0 && pos<LLC) ? p0[(b*NMC+c)*LLC+pos] : 0.f;
                    }
                    v = make_float4(t[0],t[1],t[2],t[3]);
                } else {
                    v = *(const float4*)&A[m*lda + k];
                    if (AMODE==1) {
                        float sc = rs_s[mo];
                        float4 w = *(const float4*)&p1[k];
                        v.x *= sc*w.x; v.y *= sc*w.y; v.z *= sc*w.z; v.w *= sc*w.w;
                    }
                }
            }
            ra[i][0]=f2tf(v.x); ra[i][1]=f2tf(v.y); ra[i][2]=f2tf(v.z); ra[i][3]=f2tf(v.w);
        }
        #pragma unroll
        for (int i=0;i<LB;i++){
            int s = i*THREADS + tid;
            int no = s>>2, kq = s&3;
            int n = n0+no, k = k0+kq*4;
            float4 v = make_float4(0.f,0.f,0.f,0.f);
            if (n < N && k < Ktot) v = *(const float4*)&Bw[n*ldb + k];
            rb[i][0]=f2tf(v.x); rb[i][1]=f2tf(v.y); rb[i][2]=f2tf(v.z); rb[i][3]=f2tf(v.w);
        }
    };
    auto sts = [&](int st){
        #pragma unroll
        for (int i=0;i<LA;i++){
            int s=i*THREADS+tid; int mo=s>>2, kq=s&3;
            uint32_t* dst = &As[st][mo*KS + kq*4];
            dst[0]=ra[i][0]; dst[1]=ra[i][1]; dst[2]=ra[i][2]; dst[3]=ra[i][3];
        }
        #pragma unroll
        for (int i=0;i<LB;i++){
            int s=i*THREADS+tid; int no=s>>2, kq=s&3;
            uint32_t* dst = &Bs[st][no*KS + kq*4];
            dst[0]=rb[i][0]; dst[1]=rb[i][1]; dst[2]=rb[i][2]; dst[3]=rb[i][3];
        }
    };

    const int nk = (Ktot + TBK - 1)/TBK;
    ldg(0); sts(0); __syncthreads();
    for (int kt=0; kt<nk; kt++){
        int st = kt&1;
        if (kt+1<nk) ldg((kt+1)*TBK);
        #pragma unroll
        for (int k8=0;k8<2;k8++){
            uint32_t af[2][4], bf[4][2];
            #pragma unroll
            for (int mi=0;mi<2;mi++){
                const uint32_t* base = &As[st][(mw + mi*16 + gr)*KS + k8*8 + gc];
                af[mi][0]=base[0]; af[mi][1]=base[8*KS];
                af[mi][2]=base[4]; af[mi][3]=base[8*KS+4];
            }
            #pragma unroll
            for (int ni=0;ni<4;ni++){
                const uint32_t* base = &Bs[st][(nw + ni*8 + gr)*KS + k8*8 + gc];
                bf[ni][0]=base[0]; bf[ni][1]=base[4];
            }
            #pragma unroll
            for (int mi=0;mi<2;mi++)
                #pragma unroll
                for (int ni=0;ni<4;ni++)
                    mma_tf32(acc[mi][ni], af[mi], bf[ni]);
        }
        if (kt+1<nk){ sts(st^1); __syncthreads(); }
    }

    #pragma unroll
    for (int mi=0;mi<2;mi++){
        #pragma unroll
        for (int ni=0;ni<4;ni++){
            int n = n0 + nw + ni*8 + gc*2;
            if (n >= N) continue;
            #pragma unroll
            for (int half=0; half<2; half++){
                int m = m0 + mw + mi*16 + gr + half*8;
                if (m >= M) continue;
                float v0 = acc[mi][ni][half*2+0];
                float v1 = acc[mi][ni][half*2+1];
                if (EPI==1){
                    float t0 = v0 + p2[n];
                    t0 = (t0 - p3[n]) * rsqrtf(p4[n]+EPSF) * p5[n] + p6[n];
                    v0 = siluf(t0);
                    float t1 = v1 + p2[n+1];
                    t1 = (t1 - p3[n+1]) * rsqrtf(p4[n+1]+EPSF) * p5[n+1] + p6[n+1];
                    v1 = siluf(t1);
                }
                *(float2*)&C[m*ldc+n] = make_float2(v0, v1);
            }
        }
    }
}

// =================================================================
// gemmks: TF32 GEMM with warp-split-K (KSPLIT=2), TBK=32
// AMODE: 0 plain, 4 fused depthwise conv+silu over g_xz (side-writes g_xc)
// EPI:   0 plain, 2 residual add into C
// =================================================================
template<int TBM, int TBN, int AMODE, int EPI>
__global__ void __launch_bounds__((TBM/32)*(TBN/32)*64) gemmks(
    const float* __restrict__ A, const float* __restrict__ Bw, float* __restrict__ C,
    int M, int N, int Ktot, int lda, int ldb, int ldc,
    const float* __restrict__ p1, const float* __restrict__ p2)
{
    constexpr int TBK = 32;
    constexpr int KS = TBK + 4;
    constexpr int WN = TBN/32;
    constexpr int NOUT = (TBM/32)*(TBN/32);
    constexpr int THREADS = NOUT*64;
    constexpr int LA = TBM*TBK/(4*THREADS);
    constexpr int LB = TBN*TBK/(4*THREADS);
    constexpr int GEMM_BYTES = 2*(TBM+TBN)*KS*4;
    constexpr int RED_BYTES  = NOUT*32*33*4;
    constexpr int SMB = GEMM_BYTES > RED_BYTES ? GEMM_BYTES : RED_BYTES;
    __shared__ __align__(16) char smbuf[SMB];
    uint32_t* Asp = (uint32_t*)smbuf;
    uint32_t* Bsp = Asp + 2*TBM*KS;

    const int tid = threadIdx.x;
    const int warp = tid >> 5, lane = tid & 31;
    const int kg = warp / NOUT;
    const int wo = warp % NOUT;
    const int wr = wo / WN, wc = wo % WN;
    const int m0 = blockIdx.x*TBM, n0 = blockIdx.y*TBN;
    const int mw = wr*32, nw = wc*32;
    const int gr = lane >> 2, gc = lane & 3;

    float acc[2][4][4];
    #pragma unroll
    for (int i=0;i<2;i++)
        #pragma unroll
        for (int j=0;j<4;j++)
            #pragma unroll
            for (int q=0;q<4;q++) acc[i][j][q]=0.f;

    uint32_t ra[LA][4], rb[LB][4];

    auto ldg = [&](int k0){
        #pragma unroll
        for (int i=0;i<LA;i++){
            int s = i*THREADS + tid;
            int mo = s>>3, kq = s&7;
            int m = m0+mo, k = k0 + kq*4;
            float4 v = make_float4(0.f,0.f,0.f,0.f);
            if (m < M && k < Ktot) {
                if (AMODE==4) {
                    int l = m % LLC;
                    v = *(const float4*)&p2[k];
                    float4 w0 = *(const float4*)&p1[(k+0)*4];
                    float4 w1 = *(const float4*)&p1[(k+1)*4];
                    float4 w2 = *(const float4*)&p1[(k+2)*4];
                    float4 w3 = *(const float4*)&p1[(k+3)*4];
                    const float* wj[4] = {&w0.x, &w1.x, &w2.x, &w3.x};
                    #pragma unroll
                    for (int t=0;t<4;t++){
                        if (l - 3 + t >= 0) {
                            float4 xv = *(const float4*)&A[(m-3+t)*(2*EDC) + k];
                            v.x += xv.x * wj[0][t];
                            v.y += xv.y * wj[1][t];
                            v.z += xv.z * wj[2][t];
                            v.w += xv.w * wj[3][t];
                        }
                    }
                    v.x = siluf(v.x); v.y = siluf(v.y);
                    v.z = siluf(v.z); v.w = siluf(v.w);
                    *(float4*)&g_xc[m*EDC + k] = v;
                } else {
                    v = *(const float4*)&A[m*lda + k];
                }
            }
            ra[i][0]=f2tf(v.x); ra[i][1]=f2tf(v.y); ra[i][2]=f2tf(v.z); ra[i][3]=f2tf(v.w);
        }
        #pragma unroll
        for (int i=0;i<LB;i++){
            int s = i*THREADS + tid;
            int no = s>>3, kq = s&7;
            int n = n0+no, k = k0+kq*4;
            float4 v = make_float4(0.f,0.f,0.f,0.f);
            if (n < N && k < Ktot) v = *(const float4*)&Bw[n*ldb + k];
            rb[i][0]=f2tf(v.x); rb[i][1]=f2tf(v.y); rb[i][2]=f2tf(v.z); rb[i][3]=f2tf(v.w);
        }
    };
    auto sts = [&](int st){
        #pragma unroll
        for (int i=0;i<LA;i++){
            int s=i*THREADS+tid; int mo=s>>3, kq=s&7;
            uint32_t* dst = &Asp[st*TBM*KS + mo*KS + kq*4];
            dst[0]=ra[i][0]; dst[1]=ra[i][1]; dst[2]=ra[i][2]; dst[3]=ra[i][3];
        }
        #pragma unroll
        for (int i=0;i<LB;i++){
            int s=i*THREADS+tid; int no=s>>3, kq=s&7;
            uint32_t* dst = &Bsp[st*TBN*KS + no*KS + kq*4];
            dst[0]=rb[i][0]; dst[1]=rb[i][1]; dst[2]=rb[i][2]; dst[3]=rb[i][3];
        }
    };

    const int nkt = Ktot/TBK;
    ldg(0); sts(0); __syncthreads();
    for (int kt=0; kt<nkt; kt++){
        int st = kt&1;
        if (kt+1<nkt) ldg((kt+1)*TBK);
        #pragma unroll
        for (int k8=0;k8<2;k8++){
            int col = kg*16 + k8*8;
            uint32_t af[2][4], bf[4][2];
            #pragma unroll
            for (int mi=0;mi<2;mi++){
                const uint32_t* base = &Asp[st*TBM*KS + (mw + mi*16 + gr)*KS + col + gc];
                af[mi][0]=base[0]; af[mi][1]=base[8*KS];
                af[mi][2]=base[4]; af[mi][3]=base[8*KS+4];
            }
            #pragma unroll
            for (int ni=0;ni<4;ni++){
                const uint32_t* base = &Bsp[st*TBN*KS + (nw + ni*8 + gr)*KS + col + gc];
                bf[ni][0]=base[0]; bf[ni][1]=base[4];
            }
            #pragma unroll
            for (int mi=0;mi<2;mi++)
                #pragma unroll
                for (int ni=0;ni<4;ni++)
                    mma_tf32(acc[mi][ni], af[mi], bf[ni]);
        }
        if (kt+1<nkt){ sts(st^1); __syncthreads(); }
    }

    __syncthreads();
    float* red = (float*)smbuf;
    if (kg==1){
        #pragma unroll
        for (int mi=0;mi<2;mi++)
            #pragma unroll
            for (int ni=0;ni<4;ni++)
                #pragma unroll
                for (int q=0;q<4;q++)
                    red[(wo*32+lane)*33 + mi*16+ni*4+q] = acc[mi][ni][q];
    }
    __syncthreads();
    if (kg==0){
        #pragma unroll
        for (int mi=0;mi<2;mi++)
            #pragma unroll
            for (int ni=0;ni<4;ni++)
                #pragma unroll
                for (int q=0;q<4;q++)
                    acc[mi][ni][q] += red[(wo*32+lane)*33 + mi*16+ni*4+q];

        #pragma unroll
        for (int mi=0;mi<2;mi++){
            #pragma unroll
            for (int ni=0;ni<4;ni++){
                int n = n0 + nw + ni*8 + gc*2;
                if (n >= N) continue;
                #pragma unroll
                for (int half=0; half<2; half++){
                    int m = m0 + mw + mi*16 + gr + half*8;
                    if (m >= M) continue;
                    float v0 = acc[mi][ni][half*2+0];
                    float v1 = acc[mi][ni][half*2+1];
                    if (EPI==2){
                        float2 c = *(const float2*)&C[m*ldc+n];
                        v0 += c.x; v1 += c.y;
                    }
                    *(float2*)&C[m*ldc+n] = make_float2(v0, v1);
                }
            }
        }
    }
}

// ---------------- single-pass scan: smem-staged working set + aggregate lookback
__device__ __forceinline__ float softplusf(float a){
    return (a > 20.f) ? a : __logf(1.f + __expf(a));
}

// log-depth powers: w[k] = t1^(k+1), k = 0..15
__device__ __forceinline__ void pow16(float t1, float* w){
    float t2 = t1*t1, t4 = t2*t2, t8 = t4*t4;
    w[0]=t1; w[1]=t2; w[2]=t2*t1; w[3]=t4;
    w[4]=t4*w[0]; w[5]=t4*w[1]; w[6]=t4*w[2]; w[7]=t8;
    #pragma unroll
    for (int k=0;k<8;k++) w[8+k] = t8*w[k];
}

__global__ void __launch_bounds__(128) scan_sp(
    const float* __restrict__ Alog, const float* __restrict__ Dp,
    const float* __restrict__ dtW, const float* __restrict__ dtb)
{
    __shared__ float s_sz[CLEN][128];        // silu(z)      12.8 KB
    __shared__ float s_xin[CLEN][128];       // conv output  12.8 KB
    __shared__ float s_dbc[CLEN*PDIM];       // dbc chunk     4 KB
    __shared__ unsigned long long s_t;
    const int tid = threadIdx.x;
    if (tid==0) s_t = atomicAdd(&g_ticket, 1ULL);
    __syncthreads();
    const unsigned long long tk = s_t;
    const int pos = (int)(tk % STOT);
    const unsigned tag = (unsigned)(tk / STOT) + 1u;
    const int c   = pos / (BSZ*EGRP);
    const int rem = pos % (BSZ*EGRP);
    const int b   = rem / EGRP, eg = rem % EGRP;
    const int e   = eg*128 + tid;
    const int fibase = (b*EGRP + eg)*CHUNKS;

    const int l0 = c*CLEN;
    const float* xcp = g_xc  + (b*LLC+l0)*EDC + e;
    const float* dbcg = g_dbc + (b*LLC+l0)*PDIM;
    const float* zp  = g_xz  + (b*LLC+l0)*(2*EDC) + EDC + e;
    float* yo = g_y + (b*LLC+l0)*EDC + e;

    // ---- cooperative smem staging (all coalesced) ----
    #pragma unroll
    for (int i = 0; i < (CLEN*PDIM + 127)/128; i++) {
        int idx = i*128 + tid;
        if (idx < CLEN*PDIM) s_dbc[idx] = dbcg[idx];
    }
    #pragma unroll 5
    for (int l = 0; l < CLEN; l++) {
        s_xin[l][tid] = xcp[l*EDC];
        s_sz[l][tid]  = siluf(zp[l*(2*EDC)]);
    }
    __syncthreads();

    float a0 = -__expf(Alog[e*NSC]);
    bool ok = true;
    #pragma unroll
    for (int n = 0; n < NSC; n++) {
        float an = -__expf(Alog[e*NSC + n]);
        if (fabsf(an - a0*(float)(n+1)) > 1e-4f*fmaxf(1.f, fabsf(an))) ok = false;
    }
    float dw[DTRC];
    *(float4*)&dw[0] = *(const float4*)&dtW[e*DTRC];
    *(float4*)&dw[4] = *(const float4*)&dtW[e*DTRC+4];
    const float dbias = dtb[e];
    const float Dv = Dp[e];

    float h[NSC];
    #pragma unroll
    for (int n = 0; n < NSC; n++) h[n] = 0.f;
    float S[CLEN];
    float Sc = 0.f;

    // ---- local scan sweep (pure smem + compute) ----
    #pragma unroll 5
    for (int l = 0; l < CLEN; l++) {
        const float* row = &s_dbc[l*PDIM];
        float dacc = dbias;
        #pragma unroll
        for (int r = 0; r < DTRC; r++) dacc += row[r]*dw[r];
        float d = softplusf(dacc);
        Sc += d;
        S[l] = Sc;
        float xv = s_xin[l][tid];
        float dx = d*xv;
        float ys0 = 0.f, ys1 = 0.f;
        if (ok) {
            float w[NSC];
            pow16(__expf(d * a0), w);
            #pragma unroll
            for (int n = 0; n < NSC; n++) {
                h[n] = w[n]*h[n] + dx*row[DTRC + n];
                float t = h[n]*row[DTRC + NSC + n];
                if (n & 1) ys1 += t; else ys0 += t;
            }
        } else {
            #pragma unroll
            for (int n = 0; n < NSC; n++) {
                float dA = __expf(d * (-__expf(Alog[e*NSC + n])));
                h[n] = dA*h[n] + dx*row[DTRC + n];
                ys0 += h[n]*row[DTRC + NSC + n];
            }
        }
        yo[l*EDC] = (ys0 + ys1 + Dv*xv) * s_sz[l][tid];
    }

    // ---- publish LOCAL aggregates immediately ----
    if (c < CHUNKS-1) {
        const int base = ((b*CHUNKS + c)*NSC)*EDC + e;
        if (ok) {
            float w[NSC];
            pow16(__expf(a0*Sc), w);
            #pragma unroll
            for (int n = 0; n < NSC; n++) {
                g_cA[base + n*EDC] = w[n];
                g_cB[base + n*EDC] = h[n];
            }
        } else {
            #pragma unroll
            for (int n = 0; n < NSC; n++) {
                float an = -__expf(Alog[e*NSC + n]);
                g_cA[base + n*EDC] = __expf(an*Sc);
                g_cB[base + n*EDC] = h[n];
            }
        }
        __threadfence();
        __syncthreads();
        if (tid == 0) ((volatile unsigned*)g_sflag)[fibase + c] = tag;
    }

    if (c == 0) return;

    // ---- parallel wait: thread j polls predecessor j's flag ----
    if (tid < c) {
        volatile unsigned* fl = (volatile unsigned*)g_sflag;
        while (fl[fibase + tid] != tag) { __nanosleep(40); }
    }
    __syncthreads();
    __threadfence();

    // ---- fold predecessors' aggregates: h_init ----
    float hi[NSC];
    #pragma unroll
    for (int n = 0; n < NSC; n++) hi[n] = 0.f;
    for (int j = 0; j < c; j++) {
        const int base = ((b*CHUNKS + j)*NSC)*EDC + e;
        #pragma unroll
        for (int n = 0; n < NSC; n++)
            hi[n] = g_cA[base + n*EDC]*hi[n] + g_cB[base + n*EDC];
    }

    // ---- correction sweep (smem-only reads) ----
    if (ok) {
        #pragma unroll 5
        for (int l = 0; l < CLEN; l++) {
            const float* row = &s_dbc[l*PDIM];
            float w[NSC];
            pow16(__expf(a0*S[l]), w);
            float c0 = 0.f, c1 = 0.f;
            #pragma unroll
            for (int n = 0; n < NSC; n++) {
                float t = w[n]*hi[n]*row[DTRC + NSC + n];
                if (n & 1) c1 += t; else c0 += t;
            }
            yo[l*EDC] += (c0 + c1) * s_sz[l][tid];
        }
    } else {
        float an[NSC];
        #pragma unroll
        for (int n = 0; n < NSC; n++) an[n] = -__expf(Alog[e*NSC + n]);
        for (int l = 0; l < CLEN; l++) {
            const float* row = &s_dbc[l*PDIM];
            float corr = 0.f;
            #pragma unroll
            for (int n = 0; n < NSC; n++)
                corr += __expf(an[n]*S[l])*hi[n]*row[DTRC + NSC + n];
            yo[l*EDC] += corr * s_sz[l][tid];
        }
    }
}

// ---------------- tail kernels ----------------
__global__ void __launch_bounds__(128) pool2_k() {
    __shared__ float s_mu[PLEN], s_rs[PLEN];
    const int b = blockIdx.x, g = blockIdx.y;
    const int tid = threadIdx.x;
    const int warp = tid >> 5, lane = tid & 31;
    const int mbase = b*LLC + g*PLEN;

    for (int l = warp; l < PLEN; l += 4) {
        float4 v = ((const float4*)(g_x + (mbase+l)*DMC))[lane];
        float s  = v.x + v.y + v.z + v.w;
        float s2 = v.x*v.x + v.y*v.y + v.z*v.z + v.w*v.w;
        #pragma unroll
        for (int off = 16; off > 0; off >>= 1) {
            s  += __shfl_xor_sync(0xffffffffu, s,  off);
            s2 += __shfl_xor_sync(0xffffffffu, s2, off);
        }
        if (lane == 0) {
            float mu = s * (1.f/DMC);
            float var = s2 * (1.f/DMC) - mu*mu;
            s_mu[l] = mu;
            s_rs[l] = rsqrtf(var + EPSF);
        }
    }
    __syncthreads();

    const int d = tid;
    float s = 0.f;
    #pragma unroll 5
    for (int l = 0; l < PLEN; l++)
        s += (g_x[(mbase+l)*DMC + d] - s_mu[l]) * s_rs[l];
    g_pooled_pp[(b*PGRP + g)*DMC + d] = s;
}

__global__ void head_k(const float* __restrict__ lw, const float* __restrict__ lb,
                       const float* __restrict__ eW, const float* __restrict__ eb,
                       const float* __restrict__ cW, const float* __restrict__ cb,
                       const float* __restrict__ wW, const float* __restrict__ wb,
                       float* __restrict__ out) {
    __shared__ float ps[DMC], es[DMC];
    int b = blockIdx.x, t = threadIdx.x;
    float s = 0.f;
    #pragma unroll
    for (int g = 0; g < PGRP; g++) s += g_pooled_pp[(b*PGRP + g)*DMC + t];
    ps[t] = s * (1.f/LLC) * lw[t] + lb[t];
    __syncthreads();
    float acc = eb[t];
    #pragma unroll 4
    for (int k = 0; k < DMC; k++) acc += ps[k]*eW[t*DMC + k];
    float em = acc / (1.f + expf(-acc));
    es[t] = em;
    out[BSZ*NCC + BSZ + b*DMC + t] = em;
    __syncthreads();
    if (t < NCC) {
        float a = cb[t];
        #pragma unroll 4
        for (int k = 0; k < DMC; k++) a += es[k]*cW[t*DMC + k];
        out[b*NCC + t] = a;
    }
    if (t == NCC) {
        float a = wb[0];
        #pragma unroll 4
        for (int k = 0; k < DMC; k++) a += es[k]*wW[k];
        out[BSZ*NCC + b] = a;
    }
}

// ---------------- launch ----------------
extern "C" void kernel_launch(void* const* d_in, const int* in_sizes, int n_in,
                              void* d_out, int out_size) {
    const float* feat    = (const float*)d_in[0];
    const float* stem_w  = (const float*)d_in[1];
    const float* stem_b  = (const float*)d_in[2];
    const float* bn_g    = (const float*)d_in[3];
    const float* bn_b    = (const float*)d_in[4];
    const float* bn_m    = (const float*)d_in[5];
    const float* bn_v    = (const float*)d_in[6];
    const float* norm_w  = (const float*)d_in[7];
    const float* inW     = (const float*)d_in[8];
    const float* convw   = (const float*)d_in[9];
    const float* convb   = (const float*)d_in[10];
    const float* xW      = (const float*)d_in[11];
    const float* dtW     = (const float*)d_in[12];
    const float* dtb     = (const float*)d_in[13];
    const float* Alog    = (const float*)d_in[14];
    const float* Dp      = (const float*)d_in[15];
    const float* oW      = (const float*)d_in[16];
    const float* ln_w    = (const float*)d_in[17];
    const float* ln_b    = (const float*)d_in[18];
    const float* eW      = (const float*)d_in[19];
    const float* eb      = (const float*)d_in[20];
    const float* cW      = (const float*)d_in[21];
    const float* cb      = (const float*)d_in[22];
    const float* wW      = (const float*)d_in[23];
    const float* wb      = (const float*)d_in[24];
    float* out = (float*)d_out;

    static float *px=nullptr, *pxz=nullptr, *pdbc=nullptr, *py=nullptr;
    if (!px) {
        cudaGetSymbolAddress((void**)&px,   g_x);
        cudaGetSymbolAddress((void**)&pxz,  g_xz);
        cudaGetSymbolAddress((void**)&pdbc, g_dbc);
        cudaGetSymbolAddress((void**)&py,   g_y);
    }

    const int MT64 = MROWS/64;   // 125
    const int MT32 = MROWS/32;   // 250

    // stem: M=8000, N=128, K=400 (gathered A) + BN + silu -> g_x
    gemmtf<64,64,3,1><<<dim3(MT64, DMC/64), 128>>>(
        nullptr, stem_w, px, MROWS, DMC, NMC*5, 0, NMC*5, DMC,
        feat, nullptr, stem_b, bn_m, bn_v, bn_g, bn_b);

    for (int i = 0; i < NLC; i++) {
        const float* nw_i  = norm_w + i*DMC;
        const float* inW_i = inW    + i*(2*EDC)*DMC;
        const float* cw_i  = convw  + i*EDC*4;
        const float* cb_i  = convb  + i*EDC;
        const float* xW_i  = xW     + i*PDIM*EDC;
        const float* dtW_i = dtW    + i*EDC*DTRC;
        const float* dtb_i = dtb    + i*EDC;
        const float* Al_i  = Alog   + i*EDC*NSC;
        const float* D_i   = Dp     + i*EDC;
        const float* oW_i  = oW     + i*DMC*EDC;

        // rmsnorm(prologue) + in_proj: M=8000, N=512, K=128 -> g_xz
        gemmtf<64,64,1,0><<<dim3(MT64, (2*EDC)/64), 128>>>(
            px, inW_i, pxz, MROWS, 2*EDC, DMC, DMC, DMC, 2*EDC,
            nullptr, nw_i, nullptr, nullptr, nullptr, nullptr, nullptr);
        // fused conv+silu (side-writes g_xc) + x_proj -> g_dbc
        gemmks<32,64,4,0><<<dim3(MT32, 1), 128>>>(
            pxz, xW_i, pdbc, MROWS, PDIM, EDC, 2*EDC, EDC, PDIM, cw_i, cb_i);
        // single-pass scan (smem-staged), aggregate lookback, gated y -> g_y
        scan_sp<<<STOT, 128>>>(Al_i, D_i, dtW_i, dtb_i);
        // out_proj + residual -> g_x
        gemmks<32,128,0,2><<<dim3(MT32, 1), 256>>>(
            py, oW_i, px, MROWS, DMC, EDC, EDC, EDC, DMC, nullptr, nullptr);
    }

    pool2_k<<<dim3(BSZ, PGRP), 128>>>();
    head_k<<<BSZ, DMC>>>(ln_w, ln_b, eW, eb, cW, cb, wW, wb, out);
    (void)in_sizes; (void)n_in; (void)out_size;
}